// round 2
// baseline (speedup 1.0000x reference)
#include <cuda_runtime.h>
#include <cstdint>

#define MMEM 8192
#define FDIM 512
#define NQ   32768
#define EPSD 1e-12f

#define BM 64
#define BK 8
#define NTHREADS 512
#define NT (MMEM / BK)

// ---------------- scratch (__device__ globals; no allocation) ----------------
__device__ float4 g_posn[MMEM];          // normalized positions
__device__ float4 g_embn[MMEM];          // normalized position_embeddings
__device__ float4 g_pos4[MMEM];          // raw positions, padded
__device__ float  g_srow[MMEM];          // row sums of exp(sim)
__device__ float4 g_npe[MMEM];           // new_pos_emb, .w = |p|^2
__device__ float  g_memory[MMEM * FDIM]; // attn @ features

// ---------------- packed fp32x2 helpers (FFMA2 path) ----------------
__device__ __forceinline__ unsigned long long pack_dup(float v) {
    unsigned long long r;
    asm("mov.b64 %0, {%1, %1};" : "=l"(r) : "f"(v));
    return r;
}
__device__ __forceinline__ void fma2(unsigned long long& d,
                                     unsigned long long a,
                                     unsigned long long b) {
    asm("fma.rn.f32x2 %0, %1, %2, %0;" : "+l"(d) : "l"(a), "l"(b));
}

// ---------------- prep: normalize positions & embeddings ----------------
__global__ void prep_kernel(const float* __restrict__ pos,
                            const float* __restrict__ emb) {
    int i = blockIdx.x * blockDim.x + threadIdx.x;
    if (i >= MMEM) return;
    float x = pos[3 * i + 0], y = pos[3 * i + 1], z = pos[3 * i + 2];
    float inv = rsqrtf(x * x + y * y + z * z);
    g_posn[i] = make_float4(x * inv, y * inv, z * inv, 0.f);
    g_pos4[i] = make_float4(x, y, z, 0.f);
    float a = emb[3 * i + 0], b = emb[3 * i + 1], c = emb[3 * i + 2];
    float inv2 = rsqrtf(a * a + b * b + c * c);
    g_embn[i] = make_float4(a * inv2, b * inv2, c * inv2, 0.f);
}

// ---------------- fused softmax-GEMM ----------------
// MODE 0 (update): W[r,k] = exp( posn[r] . embn[k] ),           B = features,  C = g_memory, writes g_srow
// MODE 1 (query) : W[r,k] = exp( -sqrt(max(|q|^2+|p|^2-2q.p, eps)) ), B = g_memory, C = d_out
// C = rownorm(W) @ B, row sums accumulated in-kernel (BN = full 512 width per CTA).
template <int MODE>
__global__ __launch_bounds__(NTHREADS, 1)
void fused_gemm(const float* __restrict__ qraw,
                const float* __restrict__ Bin,
                float* __restrict__ Cout) {
    __shared__ __align__(16) float4 q_s[BM];
    __shared__ __align__(16) float Ws[2][BK][BM];
    __shared__ __align__(16) float Bs[2][BK][FDIM];
    __shared__ __align__(16) float s_red[BK][BM];
    __shared__ float s_fin[BM];

    const int tid  = threadIdx.x;
    const int row0 = blockIdx.x * BM;

    const float* Bmat = (MODE == 0) ? Bin : (const float*)g_memory;
    const float4* kp_arr = (MODE == 0) ? g_embn : g_npe;

    if (tid < BM) {
        int r = row0 + tid;
        if (MODE == 0) {
            q_s[tid] = g_posn[r];
        } else {
            float x = qraw[3 * r + 0], y = qraw[3 * r + 1], z = qraw[3 * r + 2];
            q_s[tid] = make_float4(x, y, z, x * x + y * y + z * z);
        }
    }
    __syncthreads();

    const int wrow = tid & 63;   // which of 64 rows this thread's weight belongs to
    const int wkk  = tid >> 6;   // which of BK=8 k-slices
    const float4 q = q_s[wrow];

    const int bcol = (tid & 63) * 8;         // B columns this thread loads
    const float4* Bp = (const float4*)Bmat;  // [8192][128] float4 view

    const int tr = tid >> 6;     // row-group (8 rows each)
    const int tc = tid & 63;     // col-group (8 cols each)

    unsigned long long acc[8][4];
#pragma unroll
    for (int i = 0; i < 8; i++)
#pragma unroll
        for (int j = 0; j < 4; j++) acc[i][j] = 0ull;

    // weight function
    auto wfun = [&](const float4 kp) -> float {
        float d = q.x * kp.x + q.y * kp.y + q.z * kp.z;
        if (MODE == 0) return __expf(d);
        float d2 = fmaxf(q.w + kp.w - 2.0f * d, EPSD);
        return __expf(-sqrtf(d2));
    };

    float s_part;
    // prologue: tile 0
    {
        float4 kp = __ldg(&kp_arr[wkk]);
        float4 b0 = __ldg(&Bp[(size_t)wkk * (FDIM / 4) + (bcol >> 2)]);
        float4 b1 = __ldg(&Bp[(size_t)wkk * (FDIM / 4) + (bcol >> 2) + 1]);
        float w = wfun(kp);
        s_part = w;
        Ws[0][wkk][wrow] = w;
        *(float4*)&Bs[0][wkk][bcol]     = b0;
        *(float4*)&Bs[0][wkk][bcol + 4] = b1;
    }
    __syncthreads();

    for (int kt = 0; kt < NT; kt++) {
        const int buf = kt & 1;
        float4 kp, b0, b1;
        const bool has = (kt + 1 < NT);
        if (has) {
            int k0 = (kt + 1) * BK;
            kp = __ldg(&kp_arr[k0 + wkk]);
            b0 = __ldg(&Bp[(size_t)(k0 + wkk) * (FDIM / 4) + (bcol >> 2)]);
            b1 = __ldg(&Bp[(size_t)(k0 + wkk) * (FDIM / 4) + (bcol >> 2) + 1]);
        }
#pragma unroll
        for (int kk = 0; kk < BK; kk++) {
            float a[8];
            *(float4*)&a[0] = *(const float4*)&Ws[buf][kk][tr * 8];
            *(float4*)&a[4] = *(const float4*)&Ws[buf][kk][tr * 8 + 4];
            ulonglong2 bq0 = *(const ulonglong2*)&Bs[buf][kk][tc * 8];
            ulonglong2 bq1 = *(const ulonglong2*)&Bs[buf][kk][tc * 8 + 4];
            unsigned long long b2[4] = {bq0.x, bq0.y, bq1.x, bq1.y};
#pragma unroll
            for (int i = 0; i < 8; i++) {
                unsigned long long a2 = pack_dup(a[i]);
                fma2(acc[i][0], a2, b2[0]);
                fma2(acc[i][1], a2, b2[1]);
                fma2(acc[i][2], a2, b2[2]);
                fma2(acc[i][3], a2, b2[3]);
            }
        }
        if (has) {
            float w = wfun(kp);
            s_part += w;
            Ws[buf ^ 1][wkk][wrow] = w;
            *(float4*)&Bs[buf ^ 1][wkk][bcol]     = b0;
            *(float4*)&Bs[buf ^ 1][wkk][bcol + 4] = b1;
        }
        __syncthreads();
    }

    // row-sum reduction (8 partials per row)
    s_red[wkk][wrow] = s_part;
    __syncthreads();
    if (tid < BM) {
        float s = 0.f;
#pragma unroll
        for (int k = 0; k < BK; k++) s += s_red[k][tid];
        s_fin[tid] = s;
        if (MODE == 0) g_srow[row0 + tid] = s;
    }
    __syncthreads();

    // epilogue: normalize and store
#pragma unroll
    for (int i = 0; i < 8; i++) {
        int r = row0 + tr * 8 + i;
        float inv = 1.0f / s_fin[tr * 8 + i];
        float2 p0 = *(float2*)&acc[i][0];
        float2 p1 = *(float2*)&acc[i][1];
        float2 p2 = *(float2*)&acc[i][2];
        float2 p3 = *(float2*)&acc[i][3];
        float4 o0 = make_float4(p0.x * inv, p0.y * inv, p1.x * inv, p1.y * inv);
        float4 o1 = make_float4(p2.x * inv, p2.y * inv, p3.x * inv, p3.y * inv);
        float* Cr = (MODE == 0) ? &g_memory[(size_t)r * FDIM] : &Cout[(size_t)r * FDIM];
        *(float4*)&Cr[tc * 8]     = o0;
        *(float4*)&Cr[tc * 8 + 4] = o1;
    }
}

// ---------------- new_pos_emb = attn @ positions (reuses g_srow) ----------------
__global__ void posemb_kernel() {
    const int i = blockIdx.x;
    const int t = threadIdx.x;
    float4 pn = g_posn[i];
    float ax = 0.f, ay = 0.f, az = 0.f;
    for (int j = t; j < MMEM; j += 256) {
        float4 en = g_embn[j];
        float w = __expf(pn.x * en.x + pn.y * en.y + pn.z * en.z);
        float4 p = g_pos4[j];
        ax = fmaf(w, p.x, ax);
        ay = fmaf(w, p.y, ay);
        az = fmaf(w, p.z, az);
    }
    __shared__ float rx[256], ry[256], rz[256];
    rx[t] = ax; ry[t] = ay; rz[t] = az;
    __syncthreads();
    for (int s = 128; s > 0; s >>= 1) {
        if (t < s) { rx[t] += rx[t + s]; ry[t] += ry[t + s]; rz[t] += rz[t + s]; }
        __syncthreads();
    }
    if (t == 0) {
        float inv = 1.0f / g_srow[i];
        float x = rx[0] * inv, y = ry[0] * inv, z = rz[0] * inv;
        g_npe[i] = make_float4(x, y, z, x * x + y * y + z * z);
    }
}

// ---------------- launch ----------------
extern "C" void kernel_launch(void* const* d_in, const int* in_sizes, int n_in,
                              void* d_out, int out_size) {
    const float* features  = (const float*)d_in[0];  // [8192, 512]
    const float* positions = (const float*)d_in[1];  // [8192, 3]
    const float* queries   = (const float*)d_in[2];  // [32768, 3]
    const float* pemb      = (const float*)d_in[3];  // [8192, 3]

    prep_kernel<<<MMEM / 256, 256>>>(positions, pemb);
    fused_gemm<0><<<MMEM / BM, NTHREADS>>>(nullptr, features, nullptr);
    posemb_kernel<<<MMEM, 256>>>();
    fused_gemm<1><<<NQ / BM, NTHREADS>>>(queries, nullptr, (float*)d_out);
}

// round 4
// speedup vs baseline: 2.7565x; 2.7565x over previous
#include <cuda_runtime.h>
#include <cuda_fp16.h>
#include <cstdint>

#define MMEM 8192
#define FDIM 512
#define NQ   32768
#define EPSD 1e-12f

#define BM 64
#define BK 32
#define NTH 512
#define NTK (MMEM / BK)     // 256 k-tiles

// ---- smem byte offsets ----
// A[buf][half]: 64 rows x 80B (32 fp16 padded) = 5120 per plane
#define SM_A    0
#define A_BUF   10240
#define A_HALF  5120
// B[buf][half]: 32 rows x 1024B (512 fp16) = 32768 per plane
#define SM_B    20480
#define B_BUF   65536
#define B_HALF  32768
#define SM_RED  151552      // 8*64 floats
#define SM_FIN  153600      // 64 floats
#define SMEM_TOTAL 153856

// ---------------- device scratch ----------------
__device__ float4 g_posn[MMEM];
__device__ float4 g_embn[MMEM];
__device__ float4 g_pos4[MMEM];
__device__ float4 g_npe[MMEM];
__device__ float  g_memory[MMEM * FDIM];
__device__ __half g_FT_hi[MMEM * FDIM];
__device__ __half g_FT_lo[MMEM * FDIM];
__device__ __half g_MT_hi[MMEM * FDIM];
__device__ __half g_MT_lo[MMEM * FDIM];

// ---------------- PTX helpers (portable ISA only) ----------------
__device__ __forceinline__ uint32_t smem_u32(const void* p) {
    uint32_t a;
    asm("{ .reg .u64 t; cvta.to.shared.u64 t, %1; cvt.u32.u64 %0, t; }" : "=r"(a) : "l"(p));
    return a;
}
__device__ __forceinline__ void ldsm_x4(uint32_t* r, uint32_t addr) {
    asm volatile("ldmatrix.sync.aligned.m8n8.x4.shared.b16 {%0,%1,%2,%3}, [%4];"
        : "=r"(r[0]), "=r"(r[1]), "=r"(r[2]), "=r"(r[3]) : "r"(addr));
}
__device__ __forceinline__ void ldsm_x4t(uint32_t* r, uint32_t addr) {
    asm volatile("ldmatrix.sync.aligned.m8n8.x4.trans.shared.b16 {%0,%1,%2,%3}, [%4];"
        : "=r"(r[0]), "=r"(r[1]), "=r"(r[2]), "=r"(r[3]) : "r"(addr));
}
__device__ __forceinline__ void mma16816(float* c, const uint32_t* a, const uint32_t* b) {
    asm volatile("mma.sync.aligned.m16n8k16.row.col.f32.f16.f16.f32 "
        "{%0,%1,%2,%3}, {%4,%5,%6,%7}, {%8,%9}, {%0,%1,%2,%3};"
        : "+f"(c[0]), "+f"(c[1]), "+f"(c[2]), "+f"(c[3])
        : "r"(a[0]), "r"(a[1]), "r"(a[2]), "r"(a[3]), "r"(b[0]), "r"(b[1]));
}
__device__ __forceinline__ void cp16(uint32_t dst, const void* src) {
    asm volatile("cp.async.cg.shared.global [%0], [%1], 16;" :: "r"(dst), "l"(src) : "memory");
}
#define CP_COMMIT() asm volatile("cp.async.commit_group;" ::: "memory")
#define CP_WAIT0()  asm volatile("cp.async.wait_group 0;" ::: "memory")

// ---------------- prep: normalize ----------------
__global__ void prep_kernel(const float* __restrict__ pos, const float* __restrict__ emb) {
    int i = blockIdx.x * blockDim.x + threadIdx.x;
    if (i >= MMEM) return;
    float x = pos[3 * i], y = pos[3 * i + 1], z = pos[3 * i + 2];
    float inv = rsqrtf(x * x + y * y + z * z);
    g_posn[i] = make_float4(x * inv, y * inv, z * inv, 0.f);
    g_pos4[i] = make_float4(x, y, z, 0.f);
    float a = emb[3 * i], b = emb[3 * i + 1], c = emb[3 * i + 2];
    float inv2 = rsqrtf(a * a + b * b + c * c);
    g_embn[i] = make_float4(a * inv2, b * inv2, c * inv2, 0.f);
}

// ---------------- split: fp32[k][n] -> fp16 hi/lo [k][n] (no transpose) ----------------
template <int SRC>
__global__ void split_kernel(const float* __restrict__ srcArg) {
    int id = blockIdx.x * blockDim.x + threadIdx.x;   // MMEM*FDIM/8 threads
    const float4* S = (const float4*)((SRC == 0) ? srcArg : (const float*)g_memory);
    __half* Dh = (SRC == 0) ? g_FT_hi : g_MT_hi;
    __half* Dl = (SRC == 0) ? g_FT_lo : g_MT_lo;
    float4 v0 = S[id * 2], v1 = S[id * 2 + 1];
    float v[8] = {v0.x, v0.y, v0.z, v0.w, v1.x, v1.y, v1.z, v1.w};
    uint32_t ph[4], pl[4];
#pragma unroll
    for (int j = 0; j < 4; j++) {
        __half h0 = __float2half_rn(v[2 * j]), h1 = __float2half_rn(v[2 * j + 1]);
        __half l0 = __float2half_rn(v[2 * j] - __half2float(h0));
        __half l1 = __float2half_rn(v[2 * j + 1] - __half2float(h1));
        ph[j] = ((uint32_t)__half_as_ushort(h1) << 16) | __half_as_ushort(h0);
        pl[j] = ((uint32_t)__half_as_ushort(l1) << 16) | __half_as_ushort(l0);
    }
    *(uint4*)&Dh[(size_t)id * 8] = make_uint4(ph[0], ph[1], ph[2], ph[3]);
    *(uint4*)&Dl[(size_t)id * 8] = make_uint4(pl[0], pl[1], pl[2], pl[3]);
}

// ---------------- new_pos_emb (self-normalizing, 8 rows/block) ----------------
__global__ void posemb_kernel() {
    const int i0 = blockIdx.x * 8;
    const int t = threadIdx.x;
    float4 pn[8];
#pragma unroll
    for (int r = 0; r < 8; r++) pn[r] = g_posn[i0 + r];
    float ax[8] = {}, ay[8] = {}, az[8] = {}, as[8] = {};
    for (int j = t; j < MMEM; j += 256) {
        float4 en = g_embn[j];
        float4 p = g_pos4[j];
#pragma unroll
        for (int r = 0; r < 8; r++) {
            float w = __expf(pn[r].x * en.x + pn[r].y * en.y + pn[r].z * en.z);
            ax[r] = fmaf(w, p.x, ax[r]);
            ay[r] = fmaf(w, p.y, ay[r]);
            az[r] = fmaf(w, p.z, az[r]);
            as[r] += w;
        }
    }
    __shared__ float red[8][4][8];
    const int lane = t & 31, warp = t >> 5;
#pragma unroll
    for (int r = 0; r < 8; r++) {
        float v[4] = {ax[r], ay[r], az[r], as[r]};
#pragma unroll
        for (int c = 0; c < 4; c++) {
#pragma unroll
            for (int s = 16; s > 0; s >>= 1) v[c] += __shfl_down_sync(0xffffffffu, v[c], s);
            if (lane == 0) red[r][c][warp] = v[c];
        }
    }
    __syncthreads();
    if (t < 8) {
        float sx = 0, sy = 0, sz = 0, ss = 0;
#pragma unroll
        for (int w = 0; w < 8; w++) { sx += red[t][0][w]; sy += red[t][1][w]; sz += red[t][2][w]; ss += red[t][3][w]; }
        float inv = 1.0f / ss;
        float x = sx * inv, y = sy * inv, z = sz * inv;
        g_npe[i0 + t] = make_float4(x, y, z, x * x + y * y + z * z);
    }
}

// ---------------- fused softmax-GEMM on mma.sync (HMMA) ----------------
// C[BM x 512] = rownorm(W) @ B, W generated on the fly (exp of coord function),
// 3-term fp16 split: Ah*Bh + Ah*Bl + Al*Bh, exact fp32 row sums.
template <int MODE>
__global__ __launch_bounds__(NTH, 1)
void mma_gemm(const float* __restrict__ qraw, float* __restrict__ CoutQ) {
    extern __shared__ __align__(1024) char smem[];
    const uint32_t sb = smem_u32(smem);
    const int tid = threadIdx.x;
    const int wid = tid >> 5, lane = tid & 31;
    const int row0 = blockIdx.x * BM;

    // weight-gen mapping: row = tid&63, k-slice = (tid>>6)*4 + j
    const int wr = tid & 63;
    const int kq = tid >> 6;

    float4 q;
    if (MODE == 0) {
        q = g_posn[row0 + wr];
    } else {
        int r = row0 + wr;
        float x = qraw[3 * r], y = qraw[3 * r + 1], z = qraw[3 * r + 2];
        q = make_float4(x, y, z, x * x + y * y + z * z);
    }
    const float4* kp_arr = (MODE == 0) ? g_embn : g_npe;
    const __half* Bhg = (MODE == 0) ? g_FT_hi : g_MT_hi;
    const __half* Blg = (MODE == 0) ? g_FT_lo : g_MT_lo;

    // per-lane ldmatrix offsets
    const uint32_t arow  = (uint32_t)((lane & 15) * 80 + (lane >> 4) * 16);
    const uint32_t bkoff = (uint32_t)((lane & 7) * 1024 + ((lane >> 3) & 1) * 8192);
    const uint32_t bxor  = (uint32_t)((lane & 7) << 4);
    const uint32_t bnb   = (uint32_t)(wid * 64 + (lane >> 4) * 16);  // 2*n byte base

    float acc[4][4][4];
#pragma unroll
    for (int a = 0; a < 4; a++)
#pragma unroll
        for (int b = 0; b < 4; b++)
#pragma unroll
            for (int c = 0; c < 4; c++) acc[a][b][c] = 0.f;
    float s_part = 0.f;

    // ---- tile fill: cp.async B (hi+lo) + compute/store weights ----
    auto fill = [&](int kt, int buf) {
        const int k0 = kt * BK;
        // B tiles: 2048 16B-chunks per half, 4 per thread per half
#pragma unroll
        for (int half = 0; half < 2; half++) {
            const __half* src = half ? Blg : Bhg;
            const uint32_t base = sb + SM_B + buf * B_BUF + half * B_HALF;
#pragma unroll
            for (int i = 0; i < 4; i++) {
                int c = tid + i * NTH;
                int k = c >> 6, n8 = c & 63;
                uint32_t dst = base + (uint32_t)(k * 1024 + ((n8 * 16) ^ ((k & 7) << 4)));
                cp16(dst, src + (size_t)(k0 + k) * FDIM + n8 * 8);
            }
        }
        CP_COMMIT();
        // weights: 4 per thread
        float w[4];
#pragma unroll
        for (int j = 0; j < 4; j++) {
            float4 kp = __ldg(&kp_arr[k0 + kq * 4 + j]);
            float d = fmaf(q.x, kp.x, fmaf(q.y, kp.y, q.z * kp.z));
            if (MODE == 0) w[j] = __expf(d);
            else           w[j] = __expf(-sqrtf(fmaxf(q.w + kp.w - 2.f * d, EPSD)));
            s_part += w[j];
        }
        uint32_t hp[2], lp[2];
#pragma unroll
        for (int j = 0; j < 2; j++) {
            __half h0 = __float2half_rn(w[2 * j]), h1 = __float2half_rn(w[2 * j + 1]);
            __half l0 = __float2half_rn(w[2 * j] - __half2float(h0));
            __half l1 = __float2half_rn(w[2 * j + 1] - __half2float(h1));
            hp[j] = ((uint32_t)__half_as_ushort(h1) << 16) | __half_as_ushort(h0);
            lp[j] = ((uint32_t)__half_as_ushort(l1) << 16) | __half_as_ushort(l0);
        }
        uint32_t aoff = (uint32_t)(wr * 80 + kq * 8);
        *(uint2*)(smem + SM_A + buf * A_BUF + aoff)          = make_uint2(hp[0], hp[1]);
        *(uint2*)(smem + SM_A + buf * A_BUF + A_HALF + aoff) = make_uint2(lp[0], lp[1]);
    };

    // prologue
    fill(0, 0);
    CP_WAIT0();
    __syncthreads();

    for (int kt = 0; kt < NTK; kt++) {
        const int buf = kt & 1;
        if (kt + 1 < NTK) fill(kt + 1, buf ^ 1);

        const uint32_t Abase = sb + SM_A + buf * A_BUF;
        const uint32_t Bbase = sb + SM_B + buf * B_BUF;
#pragma unroll
        for (int kk = 0; kk < 2; kk++) {
            // B frags: [p][4 regs] = frags for n-subtiles p*16 .. p*16+15
            uint32_t bh[2][4], bl[2][4];
#pragma unroll
            for (int p = 0; p < 2; p++) {
                uint32_t byte0 = (bnb + p * 32) ^ bxor;
                uint32_t addr = Bbase + kk * 16384 + bkoff + byte0;
                ldsm_x4t(bh[p], addr);
                ldsm_x4t(bl[p], addr + B_HALF);
            }
#pragma unroll
            for (int mi = 0; mi < 4; mi++) {
                uint32_t ah[4], al[4];
                uint32_t aaddr = Abase + mi * 1280 + kk * 32 + arow;
                ldsm_x4(ah, aaddr);
                ldsm_x4(al, aaddr + A_HALF);
#pragma unroll
                for (int ni = 0; ni < 4; ni++) {
                    const uint32_t* bhf = &bh[ni >> 1][(ni & 1) * 2];
                    const uint32_t* blf = &bl[ni >> 1][(ni & 1) * 2];
                    mma16816(acc[mi][ni], ah, bhf);
                    mma16816(acc[mi][ni], ah, blf);
                    mma16816(acc[mi][ni], al, bhf);
                }
            }
        }
        CP_WAIT0();
        __syncthreads();
    }

    // exact fp32 row sums -> inverse
    *(float*)(smem + SM_RED + (kq * 64 + wr) * 4) = s_part;
    __syncthreads();
    if (tid < BM) {
        float s = 0.f;
#pragma unroll
        for (int k = 0; k < 8; k++) s += *(float*)(smem + SM_RED + (k * 64 + tid) * 4);
        *(float*)(smem + SM_FIN + tid * 4) = 1.0f / s;
    }
    __syncthreads();

    // epilogue
    float* Cbase = (MODE == 0) ? g_memory : CoutQ;
    const int n0 = wid * 32;
#pragma unroll
    for (int mi = 0; mi < 4; mi++) {
        int r0 = mi * 16 + (lane >> 2);
        int r1 = r0 + 8;
        float inv0 = *(float*)(smem + SM_FIN + r0 * 4);
        float inv1 = *(float*)(smem + SM_FIN + r1 * 4);
        float* C0 = Cbase + (size_t)(row0 + r0) * FDIM + n0 + (lane & 3) * 2;
        float* C1 = Cbase + (size_t)(row0 + r1) * FDIM + n0 + (lane & 3) * 2;
#pragma unroll
        for (int ni = 0; ni < 4; ni++) {
            float2 v0 = make_float2(acc[mi][ni][0] * inv0, acc[mi][ni][1] * inv0);
            float2 v1 = make_float2(acc[mi][ni][2] * inv1, acc[mi][ni][3] * inv1);
            *(float2*)(C0 + ni * 8) = v0;
            *(float2*)(C1 + ni * 8) = v1;
        }
    }
}

// ---------------- launch ----------------
extern "C" void kernel_launch(void* const* d_in, const int* in_sizes, int n_in,
                              void* d_out, int out_size) {
    (void)in_sizes; (void)n_in; (void)out_size;
    const float* features  = (const float*)d_in[0];  // [8192, 512]
    const float* positions = (const float*)d_in[1];  // [8192, 3]
    const float* queries   = (const float*)d_in[2];  // [32768, 3]
    const float* pemb      = (const float*)d_in[3];  // [8192, 3]

    static int inited = 0;
    if (!inited) {
        cudaFuncSetAttribute(mma_gemm<0>, cudaFuncAttributeMaxDynamicSharedMemorySize, SMEM_TOTAL);
        cudaFuncSetAttribute(mma_gemm<1>, cudaFuncAttributeMaxDynamicSharedMemorySize, SMEM_TOTAL);
        inited = 1;
    }

    prep_kernel<<<MMEM / 256, 256>>>(positions, pemb);
    split_kernel<0><<<(MMEM * FDIM / 8) / 256, 256>>>(features);
    posemb_kernel<<<MMEM / 8, 256>>>();
    mma_gemm<0><<<MMEM / BM, NTH, SMEM_TOTAL>>>(nullptr, nullptr);
    split_kernel<1><<<(MMEM * FDIM / 8) / 256, 256>>>(nullptr);
    mma_gemm<1><<<NQ / BM, NTH, SMEM_TOTAL>>>(queries, (float*)d_out);
}

// round 9
// speedup vs baseline: 3.3638x; 1.2203x over previous
#include <cuda_runtime.h>
#include <cuda_fp16.h>
#include <cstdint>

#define MMEM 8192
#define FDIM 512
#define NQ   32768
#define EPSD 1e-12f

#define BM 64
#define BN 256
#define BK 32
#define NTH 256
#define NTK (MMEM / BK)     // 256 k-tiles

// ---- smem byte offsets ----
// A[buf]: 64 rows x 80B (32 fp16 padded) = 5120 per buf (hi only)
#define SM_A    0
#define A_BUF   5120
// B[buf][half]: 32 rows x 512B (256 fp16) = 16384 per plane
#define SM_B    10240
#define B_BUF   32768
#define B_HALF  16384
#define SM_RED  75776       // 4*64 floats
#define SM_FIN  76800       // 64 floats
#define SMEM_TOTAL 77056

// ---------------- device scratch ----------------
__device__ float4 g_posn[MMEM];
__device__ float4 g_embn[MMEM];
__device__ float4 g_pos4[MMEM];
__device__ float4 g_npe[MMEM];
__device__ float  g_memory[MMEM * FDIM];
__device__ __half g_FT_hi[MMEM * FDIM];
__device__ __half g_FT_lo[MMEM * FDIM];
__device__ __half g_MT_hi[MMEM * FDIM];
__device__ __half g_MT_lo[MMEM * FDIM];

// ---------------- PTX helpers ----------------
__device__ __forceinline__ uint32_t smem_u32(const void* p) {
    uint32_t a;
    asm("{ .reg .u64 t; cvta.to.shared.u64 t, %1; cvt.u32.u64 %0, t; }" : "=r"(a) : "l"(p));
    return a;
}
__device__ __forceinline__ void ldsm_x4(uint32_t* r, uint32_t addr) {
    asm volatile("ldmatrix.sync.aligned.m8n8.x4.shared.b16 {%0,%1,%2,%3}, [%4];"
        : "=r"(r[0]), "=r"(r[1]), "=r"(r[2]), "=r"(r[3]) : "r"(addr));
}
__device__ __forceinline__ void ldsm_x4t(uint32_t* r, uint32_t addr) {
    asm volatile("ldmatrix.sync.aligned.m8n8.x4.trans.shared.b16 {%0,%1,%2,%3}, [%4];"
        : "=r"(r[0]), "=r"(r[1]), "=r"(r[2]), "=r"(r[3]) : "r"(addr));
}
__device__ __forceinline__ void mma16816(float* c, const uint32_t* a, const uint32_t* b) {
    asm volatile("mma.sync.aligned.m16n8k16.row.col.f32.f16.f16.f32 "
        "{%0,%1,%2,%3}, {%4,%5,%6,%7}, {%8,%9}, {%0,%1,%2,%3};"
        : "+f"(c[0]), "+f"(c[1]), "+f"(c[2]), "+f"(c[3])
        : "r"(a[0]), "r"(a[1]), "r"(a[2]), "r"(a[3]), "r"(b[0]), "r"(b[1]));
}
__device__ __forceinline__ void cp16(uint32_t dst, const void* src) {
    asm volatile("cp.async.cg.shared.global [%0], [%1], 16;" :: "r"(dst), "l"(src) : "memory");
}
#define CP_COMMIT() asm volatile("cp.async.commit_group;" ::: "memory")
#define CP_WAIT0()  asm volatile("cp.async.wait_group 0;" ::: "memory")

// ---------------- prep: normalize ----------------
__global__ void prep_kernel(const float* __restrict__ pos, const float* __restrict__ emb) {
    int i = blockIdx.x * blockDim.x + threadIdx.x;
    if (i >= MMEM) return;
    float x = pos[3 * i], y = pos[3 * i + 1], z = pos[3 * i + 2];
    float inv = rsqrtf(x * x + y * y + z * z);
    g_posn[i] = make_float4(x * inv, y * inv, z * inv, 0.f);
    g_pos4[i] = make_float4(x, y, z, 0.f);
    float a = emb[3 * i], b = emb[3 * i + 1], c = emb[3 * i + 2];
    float inv2 = rsqrtf(a * a + b * b + c * c);
    g_embn[i] = make_float4(a * inv2, b * inv2, c * inv2, 0.f);
}

// ---------------- split: fp32[k][n] -> fp16 hi/lo [k][n] ----------------
template <int SRC>
__global__ void split_kernel(const float* __restrict__ srcArg) {
    int id = blockIdx.x * blockDim.x + threadIdx.x;   // MMEM*FDIM/8 threads
    const float4* S = (const float4*)((SRC == 0) ? srcArg : (const float*)g_memory);
    __half* Dh = (SRC == 0) ? g_FT_hi : g_MT_hi;
    __half* Dl = (SRC == 0) ? g_FT_lo : g_MT_lo;
    float4 v0 = S[id * 2], v1 = S[id * 2 + 1];
    float v[8] = {v0.x, v0.y, v0.z, v0.w, v1.x, v1.y, v1.z, v1.w};
    uint32_t ph[4], pl[4];
#pragma unroll
    for (int j = 0; j < 4; j++) {
        __half h0 = __float2half_rn(v[2 * j]), h1 = __float2half_rn(v[2 * j + 1]);
        __half l0 = __float2half_rn(v[2 * j] - __half2float(h0));
        __half l1 = __float2half_rn(v[2 * j + 1] - __half2float(h1));
        ph[j] = ((uint32_t)__half_as_ushort(h1) << 16) | __half_as_ushort(h0);
        pl[j] = ((uint32_t)__half_as_ushort(l1) << 16) | __half_as_ushort(l0);
    }
    *(uint4*)&Dh[(size_t)id * 8] = make_uint4(ph[0], ph[1], ph[2], ph[3]);
    *(uint4*)&Dl[(size_t)id * 8] = make_uint4(pl[0], pl[1], pl[2], pl[3]);
}

// ---------------- new_pos_emb (self-normalizing, 8 rows/block) ----------------
__global__ void posemb_kernel() {
    const int i0 = blockIdx.x * 8;
    const int t = threadIdx.x;
    float4 pn[8];
#pragma unroll
    for (int r = 0; r < 8; r++) pn[r] = g_posn[i0 + r];
    float ax[8] = {}, ay[8] = {}, az[8] = {}, as[8] = {};
    for (int j = t; j < MMEM; j += 256) {
        float4 en = g_embn[j];
        float4 p = g_pos4[j];
#pragma unroll
        for (int r = 0; r < 8; r++) {
            float w = __expf(pn[r].x * en.x + pn[r].y * en.y + pn[r].z * en.z);
            ax[r] = fmaf(w, p.x, ax[r]);
            ay[r] = fmaf(w, p.y, ay[r]);
            az[r] = fmaf(w, p.z, az[r]);
            as[r] += w;
        }
    }
    __shared__ float red[8][4][8];
    const int lane = t & 31, warp = t >> 5;
#pragma unroll
    for (int r = 0; r < 8; r++) {
        float v[4] = {ax[r], ay[r], az[r], as[r]};
#pragma unroll
        for (int c = 0; c < 4; c++) {
#pragma unroll
            for (int s = 16; s > 0; s >>= 1) v[c] += __shfl_down_sync(0xffffffffu, v[c], s);
            if (lane == 0) red[r][c][warp] = v[c];
        }
    }
    __syncthreads();
    if (t < 8) {
        float sx = 0, sy = 0, sz = 0, ss = 0;
#pragma unroll
        for (int w = 0; w < 8; w++) { sx += red[t][0][w]; sy += red[t][1][w]; sz += red[t][2][w]; ss += red[t][3][w]; }
        float inv = 1.0f / ss;
        float x = sx * inv, y = sy * inv, z = sz * inv;
        g_npe[i0 + t] = make_float4(x, y, z, x * x + y * y + z * z);
    }
}

// ---------------- fused softmax-GEMM on mma.sync (HMMA) ----------------
// C[BM x BN] = rownorm(Wfp16) @ (Bh + Bl): 2 MMA terms. Row sums are of the
// fp16-ROUNDED weights (fp32 accumulation), so rounding largely cancels in the
// softmax ratio. BM=64, BN=256, 8 warps, 2 CTAs/SM.
template <int MODE>
__global__ __launch_bounds__(NTH, 2)
void mma_gemm(const float* __restrict__ qraw, float* __restrict__ CoutQ) {
    extern __shared__ __align__(1024) char smem[];
    const uint32_t sb = smem_u32(smem);
    const int tid = threadIdx.x;
    const int wid = tid >> 5, lane = tid & 31;
    const int row0 = (blockIdx.x >> 1) * BM;
    const int n0   = (blockIdx.x & 1) * BN;

    // weight-gen mapping: row = tid&63, k-group = (tid>>6)*8 + j (8 per thread)
    const int wr = tid & 63;
    const int kq = tid >> 6;      // 0..3

    float4 q;
    if (MODE == 0) {
        q = g_posn[row0 + wr];
    } else {
        int r = row0 + wr;
        float x = qraw[3 * r], y = qraw[3 * r + 1], z = qraw[3 * r + 2];
        q = make_float4(x, y, z, x * x + y * y + z * z);
    }
    const float4* kp_arr = (MODE == 0) ? g_embn : g_npe;
    const __half* Bhg = (MODE == 0) ? g_FT_hi : g_MT_hi;
    const __half* Blg = (MODE == 0) ? g_FT_lo : g_MT_lo;

    // warp tiling: m-half (wid>>2) owns 32 rows, n-quarter (wid&3) owns 64 cols
    const uint32_t arow  = (uint32_t)((lane & 15) * 80 + (lane >> 4) * 16);
    const uint32_t abase_w = (uint32_t)((wid >> 2) * 2560);
    const uint32_t bkoff = (uint32_t)((lane & 7) * 512 + ((lane >> 3) & 1) * 4096);
    const uint32_t bxor  = (uint32_t)((lane & 7) << 4);
    const uint32_t bnb   = (uint32_t)((wid & 3) * 128 + (lane >> 4) * 16);

    float acc[2][8][4];
#pragma unroll
    for (int a = 0; a < 2; a++)
#pragma unroll
        for (int b = 0; b < 8; b++)
#pragma unroll
            for (int c = 0; c < 4; c++) acc[a][b][c] = 0.f;
    float s_part = 0.f;

    auto fill = [&](int kt, int buf) {
        const int k0 = kt * BK;
        // B tiles: 1024 16B-chunks per half, 4 per thread per half
#pragma unroll
        for (int half = 0; half < 2; half++) {
            const __half* src = half ? Blg : Bhg;
            const uint32_t base = sb + SM_B + buf * B_BUF + half * B_HALF;
#pragma unroll
            for (int i = 0; i < 4; i++) {
                int c = tid + i * NTH;            // 0..1023
                int k = c >> 5, n8 = c & 31;
                uint32_t dst = base + (uint32_t)(k * 512 + ((n8 * 16) ^ ((k & 7) << 4)));
                cp16(dst, src + (size_t)(k0 + k) * FDIM + n0 + n8 * 8);
            }
        }
        CP_COMMIT();
        // weights: 8 per thread; sum the ROUNDED values in fp32
        uint32_t hp[4];
#pragma unroll
        for (int j2 = 0; j2 < 4; j2++) {
            float w0, w1;
#pragma unroll
            for (int u = 0; u < 2; u++) {
                float4 kp = __ldg(&kp_arr[k0 + kq * 8 + j2 * 2 + u]);
                float d = fmaf(q.x, kp.x, fmaf(q.y, kp.y, q.z * kp.z));
                float w;
                if (MODE == 0) w = __expf(d);
                else           w = __expf(-sqrtf(fmaxf(q.w + kp.w - 2.f * d, EPSD)));
                if (u == 0) w0 = w; else w1 = w;
            }
            __half h0 = __float2half_rn(w0), h1 = __float2half_rn(w1);
            s_part += __half2float(h0) + __half2float(h1);
            hp[j2] = ((uint32_t)__half_as_ushort(h1) << 16) | __half_as_ushort(h0);
        }
        *(uint4*)(smem + SM_A + buf * A_BUF + wr * 80 + kq * 16) =
            make_uint4(hp[0], hp[1], hp[2], hp[3]);
    };

    fill(0, 0);
    CP_WAIT0();
    __syncthreads();

    for (int kt = 0; kt < NTK; kt++) {
        const int buf = kt & 1;
        if (kt + 1 < NTK) fill(kt + 1, buf ^ 1);

        const uint32_t Abase = sb + SM_A + buf * A_BUF + abase_w;
        const uint32_t Bbase = sb + SM_B + buf * B_BUF;
#pragma unroll
        for (int kk = 0; kk < 2; kk++) {
            uint32_t bh[4][4], bl[4][4];
#pragma unroll
            for (int p = 0; p < 4; p++) {
                uint32_t byte0 = (bnb + p * 32) ^ bxor;
                uint32_t addr = Bbase + kk * 8192 + bkoff + byte0;
                ldsm_x4t(bh[p], addr);
                ldsm_x4t(bl[p], addr + B_HALF);
            }
            uint32_t ah[2][4];
#pragma unroll
            for (int mi = 0; mi < 2; mi++)
                ldsm_x4(ah[mi], Abase + mi * 1280 + kk * 32 + arow);
#pragma unroll
            for (int mi = 0; mi < 2; mi++)
#pragma unroll
                for (int p = 0; p < 4; p++)
#pragma unroll
                    for (int qn = 0; qn < 2; qn++) {
                        mma16816(acc[mi][p * 2 + qn], ah[mi], &bh[p][qn * 2]);
                        mma16816(acc[mi][p * 2 + qn], ah[mi], &bl[p][qn * 2]);
                    }
        }
        CP_WAIT0();
        __syncthreads();
    }

    // exact fp32 row sums of rounded weights -> inverse
    *(float*)(smem + SM_RED + (kq * 64 + wr) * 4) = s_part;
    __syncthreads();
    if (tid < BM) {
        float s = 0.f;
#pragma unroll
        for (int k = 0; k < 4; k++) s += *(float*)(smem + SM_RED + (k * 64 + tid) * 4);
        *(float*)(smem + SM_FIN + tid * 4) = 1.0f / s;
    }
    __syncthreads();

    // epilogue: warp covers rows (wid>>2)*32 + mi*16 + {lane>>2, +8}, cols (wid&3)*64
    float* Cbase = (MODE == 0) ? g_memory : CoutQ;
    const int ncol0 = n0 + (wid & 3) * 64 + (lane & 3) * 2;
#pragma unroll
    for (int mi = 0; mi < 2; mi++) {
        int r0 = (wid >> 2) * 32 + mi * 16 + (lane >> 2);
        int r1 = r0 + 8;
        float inv0 = *(float*)(smem + SM_FIN + r0 * 4);
        float inv1 = *(float*)(smem + SM_FIN + r1 * 4);
        float* C0 = Cbase + (size_t)(row0 + r0) * FDIM + ncol0;
        float* C1 = Cbase + (size_t)(row0 + r1) * FDIM + ncol0;
#pragma unroll
        for (int ni = 0; ni < 8; ni++) {
            *(float2*)(C0 + ni * 8) = make_float2(acc[mi][ni][0] * inv0, acc[mi][ni][1] * inv0);
            *(float2*)(C1 + ni * 8) = make_float2(acc[mi][ni][2] * inv1, acc[mi][ni][3] * inv1);
        }
    }
}

// ---------------- launch ----------------
extern "C" void kernel_launch(void* const* d_in, const int* in_sizes, int n_in,
                              void* d_out, int out_size) {
    (void)in_sizes; (void)n_in; (void)out_size;
    const float* features  = (const float*)d_in[0];  // [8192, 512]
    const float* positions = (const float*)d_in[1];  // [8192, 3]
    const float* queries   = (const float*)d_in[2];  // [32768, 3]
    const float* pemb      = (const float*)d_in[3];  // [8192, 3]

    cudaFuncSetAttribute(mma_gemm<0>, cudaFuncAttributeMaxDynamicSharedMemorySize, SMEM_TOTAL);
    cudaFuncSetAttribute(mma_gemm<1>, cudaFuncAttributeMaxDynamicSharedMemorySize, SMEM_TOTAL);

    prep_kernel<<<MMEM / 256, 256>>>(positions, pemb);
    split_kernel<0><<<(MMEM * FDIM / 8) / 256, 256>>>(features);
    posemb_kernel<<<MMEM / 8, 256>>>();
    mma_gemm<0><<<(MMEM / BM) * 2, NTH, SMEM_TOTAL>>>(nullptr, nullptr);
    split_kernel<1><<<(MMEM * FDIM / 8) / 256, 256>>>(nullptr);
    mma_gemm<1><<<(NQ / BM) * 2, NTH, SMEM_TOTAL>>>(queries, (float*)d_out);
}

// round 11
// speedup vs baseline: 3.5790x; 1.0640x over previous
#include <cuda_runtime.h>
#include <cuda_fp16.h>
#include <cstdint>

#define MMEM 8192
#define FDIM 512
#define NQ   32768
#define EPSD 1e-12f

#define BM 64
#define BN 256
#define BK 32
#define NTH 256
#define NTK (MMEM / BK)     // 256 k-tiles

// ---- smem byte offsets ----
// A[buf]: 64 rows x 80B (32 fp16 padded) = 5120 per buf (hi only)
#define SM_A    0
#define A_BUF   5120
// B[buf][half]: 32 rows x 512B (256 fp16) = 16384 per plane
#define SM_B    10240
#define B_BUF   32768
#define B_HALF  16384
#define SM_RED  75776       // 4*64 floats
#define SM_FIN  76800       // 64 floats
#define SMEM_TOTAL 77056

// ---------------- device scratch ----------------
__device__ float4 g_posn[MMEM];
__device__ float4 g_embn[MMEM];
__device__ float4 g_pos4[MMEM];
__device__ float4 g_npe[MMEM];
__device__ float  g_memory[MMEM * FDIM];
__device__ __half g_FT_hi[MMEM * FDIM];
__device__ __half g_FT_lo[MMEM * FDIM];
__device__ __half g_MT_hi[MMEM * FDIM];
__device__ __half g_MT_lo[MMEM * FDIM];

// ---------------- PTX helpers ----------------
__device__ __forceinline__ uint32_t smem_u32(const void* p) {
    uint32_t a;
    asm("{ .reg .u64 t; cvta.to.shared.u64 t, %1; cvt.u32.u64 %0, t; }" : "=r"(a) : "l"(p));
    return a;
}
__device__ __forceinline__ void ldsm_x4(uint32_t* r, uint32_t addr) {
    asm volatile("ldmatrix.sync.aligned.m8n8.x4.shared.b16 {%0,%1,%2,%3}, [%4];"
        : "=r"(r[0]), "=r"(r[1]), "=r"(r[2]), "=r"(r[3]) : "r"(addr));
}
__device__ __forceinline__ void ldsm_x4t(uint32_t* r, uint32_t addr) {
    asm volatile("ldmatrix.sync.aligned.m8n8.x4.trans.shared.b16 {%0,%1,%2,%3}, [%4];"
        : "=r"(r[0]), "=r"(r[1]), "=r"(r[2]), "=r"(r[3]) : "r"(addr));
}
__device__ __forceinline__ void mma16816(float* c, const uint32_t* a, const uint32_t* b) {
    asm volatile("mma.sync.aligned.m16n8k16.row.col.f32.f16.f16.f32 "
        "{%0,%1,%2,%3}, {%4,%5,%6,%7}, {%8,%9}, {%0,%1,%2,%3};"
        : "+f"(c[0]), "+f"(c[1]), "+f"(c[2]), "+f"(c[3])
        : "r"(a[0]), "r"(a[1]), "r"(a[2]), "r"(a[3]), "r"(b[0]), "r"(b[1]));
}
__device__ __forceinline__ void cp16(uint32_t dst, const void* src) {
    asm volatile("cp.async.cg.shared.global [%0], [%1], 16;" :: "r"(dst), "l"(src) : "memory");
}
#define CP_COMMIT() asm volatile("cp.async.commit_group;" ::: "memory")
#define CP_WAIT0()  asm volatile("cp.async.wait_group 0;" ::: "memory")

// ---------------- prep: normalize ----------------
__global__ void prep_kernel(const float* __restrict__ pos, const float* __restrict__ emb) {
    int i = blockIdx.x * blockDim.x + threadIdx.x;
    if (i >= MMEM) return;
    float x = pos[3 * i], y = pos[3 * i + 1], z = pos[3 * i + 2];
    float inv = rsqrtf(x * x + y * y + z * z);
    g_posn[i] = make_float4(x * inv, y * inv, z * inv, 0.f);
    g_pos4[i] = make_float4(x, y, z, 0.f);
    float a = emb[3 * i], b = emb[3 * i + 1], c = emb[3 * i + 2];
    float inv2 = rsqrtf(a * a + b * b + c * c);
    g_embn[i] = make_float4(a * inv2, b * inv2, c * inv2, 0.f);
}

// ---------------- split: fp32[k][n] -> fp16 hi/lo [k][n] ----------------
template <int SRC>
__global__ void split_kernel(const float* __restrict__ srcArg) {
    int id = blockIdx.x * blockDim.x + threadIdx.x;   // MMEM*FDIM/8 threads
    const float4* S = (const float4*)((SRC == 0) ? srcArg : (const float*)g_memory);
    __half* Dh = (SRC == 0) ? g_FT_hi : g_MT_hi;
    __half* Dl = (SRC == 0) ? g_FT_lo : g_MT_lo;
    float4 v0 = S[id * 2], v1 = S[id * 2 + 1];
    float v[8] = {v0.x, v0.y, v0.z, v0.w, v1.x, v1.y, v1.z, v1.w};
    uint32_t ph[4], pl[4];
#pragma unroll
    for (int j = 0; j < 4; j++) {
        __half h0 = __float2half_rn(v[2 * j]), h1 = __float2half_rn(v[2 * j + 1]);
        __half l0 = __float2half_rn(v[2 * j] - __half2float(h0));
        __half l1 = __float2half_rn(v[2 * j + 1] - __half2float(h1));
        ph[j] = ((uint32_t)__half_as_ushort(h1) << 16) | __half_as_ushort(h0);
        pl[j] = ((uint32_t)__half_as_ushort(l1) << 16) | __half_as_ushort(l0);
    }
    *(uint4*)&Dh[(size_t)id * 8] = make_uint4(ph[0], ph[1], ph[2], ph[3]);
    *(uint4*)&Dl[(size_t)id * 8] = make_uint4(pl[0], pl[1], pl[2], pl[3]);
}

// ---------------- new_pos_emb (self-normalizing, 8 rows/block) ----------------
__global__ void posemb_kernel() {
    const int i0 = blockIdx.x * 8;
    const int t = threadIdx.x;
    float4 pn[8];
#pragma unroll
    for (int r = 0; r < 8; r++) pn[r] = g_posn[i0 + r];
    float ax[8] = {}, ay[8] = {}, az[8] = {}, as[8] = {};
    for (int j = t; j < MMEM; j += 256) {
        float4 en = g_embn[j];
        float4 p = g_pos4[j];
#pragma unroll
        for (int r = 0; r < 8; r++) {
            float w = __expf(pn[r].x * en.x + pn[r].y * en.y + pn[r].z * en.z);
            ax[r] = fmaf(w, p.x, ax[r]);
            ay[r] = fmaf(w, p.y, ay[r]);
            az[r] = fmaf(w, p.z, az[r]);
            as[r] += w;
        }
    }
    __shared__ float red[8][4][8];
    const int lane = t & 31, warp = t >> 5;
#pragma unroll
    for (int r = 0; r < 8; r++) {
        float v[4] = {ax[r], ay[r], az[r], as[r]};
#pragma unroll
        for (int c = 0; c < 4; c++) {
#pragma unroll
            for (int s = 16; s > 0; s >>= 1) v[c] += __shfl_down_sync(0xffffffffu, v[c], s);
            if (lane == 0) red[r][c][warp] = v[c];
        }
    }
    __syncthreads();
    if (t < 8) {
        float sx = 0, sy = 0, sz = 0, ss = 0;
#pragma unroll
        for (int w = 0; w < 8; w++) { sx += red[t][0][w]; sy += red[t][1][w]; sz += red[t][2][w]; ss += red[t][3][w]; }
        float inv = 1.0f / ss;
        float x = sx * inv, y = sy * inv, z = sz * inv;
        g_npe[i0 + t] = make_float4(x, y, z, x * x + y * y + z * z);
    }
}

// ---------------- fused softmax-GEMM on mma.sync (HMMA) ----------------
// C[BM x BN] = rownorm(Wfp16) @ (Bh + Bl). Warp tiling: each of the 8 warps
// owns the full 64 rows x a private 32-col strip -> every B fragment is read
// by exactly one warp (min smem traffic), reused across 4 m-subtiles in regs.
template <int MODE>
__global__ __launch_bounds__(NTH, 2)
void mma_gemm(const float* __restrict__ qraw, float* __restrict__ CoutQ) {
    extern __shared__ __align__(1024) char smem[];
    const uint32_t sb = smem_u32(smem);
    const int tid = threadIdx.x;
    const int wid = tid >> 5, lane = tid & 31;
    const int row0 = (blockIdx.x >> 1) * BM;
    const int n0   = (blockIdx.x & 1) * BN;

    // weight-gen mapping: row = tid&63, k-group = (tid>>6)*8 + j (8 per thread)
    const int wr = tid & 63;
    const int kq = tid >> 6;      // 0..3

    float4 q;
    if (MODE == 0) {
        q = g_posn[row0 + wr];
    } else {
        int r = row0 + wr;
        float x = qraw[3 * r], y = qraw[3 * r + 1], z = qraw[3 * r + 2];
        q = make_float4(x, y, z, x * x + y * y + z * z);
    }
    const float4* kp_arr = (MODE == 0) ? g_embn : g_npe;
    const __half* Bhg = (MODE == 0) ? g_FT_hi : g_MT_hi;
    const __half* Blg = (MODE == 0) ? g_FT_lo : g_MT_lo;

    // ldmatrix lane offsets
    const uint32_t arow  = (uint32_t)((lane & 15) * 80 + (lane >> 4) * 16);
    const uint32_t bkoff = (uint32_t)((lane & 7) * 512 + ((lane >> 3) & 1) * 4096);
    const uint32_t bxor  = (uint32_t)((lane & 7) << 4);
    const uint32_t bnb   = (uint32_t)(wid * 64 + (lane >> 4) * 16);   // warp's 32-col strip

    float acc[4][4][4];     // [m16 subtile][n8 subtile][frag]
#pragma unroll
    for (int a = 0; a < 4; a++)
#pragma unroll
        for (int b = 0; b < 4; b++)
#pragma unroll
            for (int c = 0; c < 4; c++) acc[a][b][c] = 0.f;
    float s_part = 0.f;

    auto fill = [&](int kt, int buf) {
        const int k0 = kt * BK;
        // B tiles: 1024 16B-chunks per half, 4 per thread per half
#pragma unroll
        for (int half = 0; half < 2; half++) {
            const __half* src = half ? Blg : Bhg;
            const uint32_t base = sb + SM_B + buf * B_BUF + half * B_HALF;
#pragma unroll
            for (int i = 0; i < 4; i++) {
                int c = tid + i * NTH;            // 0..1023
                int k = c >> 5, n8 = c & 31;
                uint32_t dst = base + (uint32_t)(k * 512 + ((n8 * 16) ^ ((k & 7) << 4)));
                cp16(dst, src + (size_t)(k0 + k) * FDIM + n0 + n8 * 8);
            }
        }
        CP_COMMIT();
        // weights: 8 per thread; sum the ROUNDED values in fp32
        uint32_t hp[4];
#pragma unroll
        for (int j2 = 0; j2 < 4; j2++) {
            float w0, w1;
#pragma unroll
            for (int u = 0; u < 2; u++) {
                float4 kp = __ldg(&kp_arr[k0 + kq * 8 + j2 * 2 + u]);
                float d = fmaf(q.x, kp.x, fmaf(q.y, kp.y, q.z * kp.z));
                float w;
                if (MODE == 0) w = __expf(d);
                else           w = __expf(-sqrtf(fmaxf(q.w + kp.w - 2.f * d, EPSD)));
                if (u == 0) w0 = w; else w1 = w;
            }
            __half h0 = __float2half_rn(w0), h1 = __float2half_rn(w1);
            s_part += __half2float(h0) + __half2float(h1);
            hp[j2] = ((uint32_t)__half_as_ushort(h1) << 16) | __half_as_ushort(h0);
        }
        *(uint4*)(smem + SM_A + buf * A_BUF + wr * 80 + kq * 16) =
            make_uint4(hp[0], hp[1], hp[2], hp[3]);
    };

    fill(0, 0);
    CP_WAIT0();
    __syncthreads();

    for (int kt = 0; kt < NTK; kt++) {
        const int buf = kt & 1;
        if (kt + 1 < NTK) fill(kt + 1, buf ^ 1);

        const uint32_t Abase = sb + SM_A + buf * A_BUF;
        const uint32_t Bbase = sb + SM_B + buf * B_BUF;
#pragma unroll
        for (int kk = 0; kk < 2; kk++) {
            // B frags for this warp's 32 cols: 2 n16 groups, hi + lo
            uint32_t bh[2][4], bl[2][4];
#pragma unroll
            for (int p = 0; p < 2; p++) {
                uint32_t byte0 = (bnb + p * 32) ^ bxor;
                uint32_t addr = Bbase + kk * 8192 + bkoff + byte0;
                ldsm_x4t(bh[p], addr);
                ldsm_x4t(bl[p], addr + B_HALF);
            }
            // A frags for all 64 rows
            uint32_t ah[4][4];
#pragma unroll
            for (int mi = 0; mi < 4; mi++)
                ldsm_x4(ah[mi], Abase + mi * 1280 + kk * 32 + arow);
#pragma unroll
            for (int mi = 0; mi < 4; mi++)
#pragma unroll
                for (int p = 0; p < 2; p++)
#pragma unroll
                    for (int qn = 0; qn < 2; qn++) {
                        mma16816(acc[mi][p * 2 + qn], ah[mi], &bh[p][qn * 2]);
                        mma16816(acc[mi][p * 2 + qn], ah[mi], &bl[p][qn * 2]);
                    }
        }
        CP_WAIT0();
        __syncthreads();
    }

    // exact fp32 row sums of rounded weights -> inverse
    *(float*)(smem + SM_RED + (kq * 64 + wr) * 4) = s_part;
    __syncthreads();
    if (tid < BM) {
        float s = 0.f;
#pragma unroll
        for (int k = 0; k < 4; k++) s += *(float*)(smem + SM_RED + (k * 64 + tid) * 4);
        *(float*)(smem + SM_FIN + tid * 4) = 1.0f / s;
    }
    __syncthreads();

    // epilogue: warp covers rows mi*16 + {lane>>2, +8}, cols wid*32 + ni*8
    float* Cbase = (MODE == 0) ? g_memory : CoutQ;
    const int ncol0 = n0 + wid * 32 + (lane & 3) * 2;
#pragma unroll
    for (int mi = 0; mi < 4; mi++) {
        int r0 = mi * 16 + (lane >> 2);
        int r1 = r0 + 8;
        float inv0 = *(float*)(smem + SM_FIN + r0 * 4);
        float inv1 = *(float*)(smem + SM_FIN + r1 * 4);
        float* C0 = Cbase + (size_t)(row0 + r0) * FDIM + ncol0;
        float* C1 = Cbase + (size_t)(row0 + r1) * FDIM + ncol0;
#pragma unroll
        for (int ni = 0; ni < 4; ni++) {
            *(float2*)(C0 + ni * 8) = make_float2(acc[mi][ni][0] * inv0, acc[mi][ni][1] * inv0);
            *(float2*)(C1 + ni * 8) = make_float2(acc[mi][ni][2] * inv1, acc[mi][ni][3] * inv1);
        }
    }
}

// ---------------- launch ----------------
extern "C" void kernel_launch(void* const* d_in, const int* in_sizes, int n_in,
                              void* d_out, int out_size) {
    (void)in_sizes; (void)n_in; (void)out_size;
    const float* features  = (const float*)d_in[0];  // [8192, 512]
    const float* positions = (const float*)d_in[1];  // [8192, 3]
    const float* queries   = (const float*)d_in[2];  // [32768, 3]
    const float* pemb      = (const float*)d_in[3];  // [8192, 3]

    cudaFuncSetAttribute(mma_gemm<0>, cudaFuncAttributeMaxDynamicSharedMemorySize, SMEM_TOTAL);
    cudaFuncSetAttribute(mma_gemm<1>, cudaFuncAttributeMaxDynamicSharedMemorySize, SMEM_TOTAL);

    prep_kernel<<<MMEM / 256, 256>>>(positions, pemb);
    split_kernel<0><<<(MMEM * FDIM / 8) / 256, 256>>>(features);
    posemb_kernel<<<MMEM / 8, 256>>>();
    mma_gemm<0><<<(MMEM / BM) * 2, NTH, SMEM_TOTAL>>>(nullptr, nullptr);
    split_kernel<1><<<(MMEM * FDIM / 8) / 256, 256>>>(nullptr);
    mma_gemm<1><<<(NQ / BM) * 2, NTH, SMEM_TOTAL>>>(queries, (float*)d_out);
}

// round 14
// speedup vs baseline: 4.5780x; 1.2791x over previous
#include <cuda_runtime.h>
#include <cuda_fp16.h>
#include <cstdint>

#define MMEM 8192
#define FDIM 512
#define NQ   32768
#define EPSD 1e-12f

#define BM 64
#define BN 256
#define BK 64
#define NTH 256
#define NTK (MMEM / BK)     // 128 k-tiles

// ---- smem byte offsets ----
// A[buf]: 64 rows x 144B (64 fp16 = 128B data + 16B pad) = 9216 per buf
#define SM_A    0
#define A_BUF   9216
// B[buf]: 64 rows x 512B (256 fp16) = 32768 per buf (single fp16 plane)
#define SM_B    18432
#define B_BUF   32768
#define SM_RED  83968       // 4*64 floats
#define SM_FIN  84992       // 64 floats
#define SMEM_TOTAL 85248

// ---------------- device scratch ----------------
__device__ float4 g_posn[MMEM];
__device__ float4 g_embn[MMEM];
__device__ float4 g_pos4[MMEM];
__device__ float4 g_npe[MMEM];
__device__ float  g_memory[MMEM * FDIM];
__device__ __half g_FT[MMEM * FDIM];
__device__ __half g_MT[MMEM * FDIM];

// ---------------- PTX helpers ----------------
__device__ __forceinline__ uint32_t smem_u32(const void* p) {
    uint32_t a;
    asm("{ .reg .u64 t; cvta.to.shared.u64 t, %1; cvt.u32.u64 %0, t; }" : "=r"(a) : "l"(p));
    return a;
}
__device__ __forceinline__ void ldsm_x4(uint32_t* r, uint32_t addr) {
    asm volatile("ldmatrix.sync.aligned.m8n8.x4.shared.b16 {%0,%1,%2,%3}, [%4];"
        : "=r"(r[0]), "=r"(r[1]), "=r"(r[2]), "=r"(r[3]) : "r"(addr));
}
__device__ __forceinline__ void ldsm_x4t(uint32_t* r, uint32_t addr) {
    asm volatile("ldmatrix.sync.aligned.m8n8.x4.trans.shared.b16 {%0,%1,%2,%3}, [%4];"
        : "=r"(r[0]), "=r"(r[1]), "=r"(r[2]), "=r"(r[3]) : "r"(addr));
}
__device__ __forceinline__ void mma16816(float* c, const uint32_t* a, const uint32_t* b) {
    asm volatile("mma.sync.aligned.m16n8k16.row.col.f32.f16.f16.f32 "
        "{%0,%1,%2,%3}, {%4,%5,%6,%7}, {%8,%9}, {%0,%1,%2,%3};"
        : "+f"(c[0]), "+f"(c[1]), "+f"(c[2]), "+f"(c[3])
        : "r"(a[0]), "r"(a[1]), "r"(a[2]), "r"(a[3]), "r"(b[0]), "r"(b[1]));
}
__device__ __forceinline__ void cp16(uint32_t dst, const void* src) {
    asm volatile("cp.async.cg.shared.global [%0], [%1], 16;" :: "r"(dst), "l"(src) : "memory");
}
#define CP_COMMIT() asm volatile("cp.async.commit_group;" ::: "memory")
#define CP_WAIT0()  asm volatile("cp.async.wait_group 0;" ::: "memory")

// ---------------- prep: normalize ----------------
__global__ void prep_kernel(const float* __restrict__ pos, const float* __restrict__ emb) {
    int i = blockIdx.x * blockDim.x + threadIdx.x;
    if (i >= MMEM) return;
    float x = pos[3 * i], y = pos[3 * i + 1], z = pos[3 * i + 2];
    float inv = rsqrtf(x * x + y * y + z * z);
    g_posn[i] = make_float4(x * inv, y * inv, z * inv, 0.f);
    g_pos4[i] = make_float4(x, y, z, 0.f);
    float a = emb[3 * i], b = emb[3 * i + 1], c = emb[3 * i + 2];
    float inv2 = rsqrtf(a * a + b * b + c * c);
    g_embn[i] = make_float4(a * inv2, b * inv2, c * inv2, 0.f);
}

// ---------------- convert: fp32[k][n] -> fp16 [k][n] ----------------
template <int SRC>
__global__ void split_kernel(const float* __restrict__ srcArg) {
    int id = blockIdx.x * blockDim.x + threadIdx.x;   // MMEM*FDIM/8 threads
    const float4* S = (const float4*)((SRC == 0) ? srcArg : (const float*)g_memory);
    __half* Dh = (SRC == 0) ? g_FT : g_MT;
    float4 v0 = S[id * 2], v1 = S[id * 2 + 1];
    float v[8] = {v0.x, v0.y, v0.z, v0.w, v1.x, v1.y, v1.z, v1.w};
    uint32_t ph[4];
#pragma unroll
    for (int j = 0; j < 4; j++) {
        __half h0 = __float2half_rn(v[2 * j]), h1 = __float2half_rn(v[2 * j + 1]);
        ph[j] = ((uint32_t)__half_as_ushort(h1) << 16) | __half_as_ushort(h0);
    }
    *(uint4*)&Dh[(size_t)id * 8] = make_uint4(ph[0], ph[1], ph[2], ph[3]);
}

// ---------------- new_pos_emb (self-normalizing, 8 rows/block) ----------------
__global__ void posemb_kernel() {
    const int i0 = blockIdx.x * 8;
    const int t = threadIdx.x;
    float4 pn[8];
#pragma unroll
    for (int r = 0; r < 8; r++) pn[r] = g_posn[i0 + r];
    float ax[8] = {}, ay[8] = {}, az[8] = {}, as[8] = {};
    for (int j = t; j < MMEM; j += 256) {
        float4 en = g_embn[j];
        float4 p = g_pos4[j];
#pragma unroll
        for (int r = 0; r < 8; r++) {
            float w = __expf(pn[r].x * en.x + pn[r].y * en.y + pn[r].z * en.z);
            ax[r] = fmaf(w, p.x, ax[r]);
            ay[r] = fmaf(w, p.y, ay[r]);
            az[r] = fmaf(w, p.z, az[r]);
            as[r] += w;
        }
    }
    __shared__ float red[8][4][8];
    const int lane = t & 31, warp = t >> 5;
#pragma unroll
    for (int r = 0; r < 8; r++) {
        float v[4] = {ax[r], ay[r], az[r], as[r]};
#pragma unroll
        for (int c = 0; c < 4; c++) {
#pragma unroll
            for (int s = 16; s > 0; s >>= 1) v[c] += __shfl_down_sync(0xffffffffu, v[c], s);
            if (lane == 0) red[r][c][warp] = v[c];
        }
    }
    __syncthreads();
    if (t < 8) {
        float sx = 0, sy = 0, sz = 0, ss = 0;
#pragma unroll
        for (int w = 0; w < 8; w++) { sx += red[t][0][w]; sy += red[t][1][w]; sz += red[t][2][w]; ss += red[t][3][w]; }
        float inv = 1.0f / ss;
        float x = sx * inv, y = sy * inv, z = sz * inv;
        g_npe[i0 + t] = make_float4(x, y, z, x * x + y * y + z * z);
    }
}

// ---------------- fused softmax-GEMM on mma.sync (HMMA) ----------------
// C[BM x BN] = rownorm(Wfp16) @ Bfp16 (single term). Normalizer = exact fp32
// sum of the fp16-ROUNDED weights, so W rounding cancels in the ratio.
// BK=64 tiles (half the barriers), 8 warps each owning 64 rows x 32 cols.
template <int MODE>
__global__ __launch_bounds__(NTH, 2)
void mma_gemm(const float* __restrict__ qraw, float* __restrict__ CoutQ) {
    extern __shared__ __align__(1024) char smem[];
    const uint32_t sb = smem_u32(smem);
    const int tid = threadIdx.x;
    const int wid = tid >> 5, lane = tid & 31;
    const int row0 = (blockIdx.x >> 1) * BM;
    const int n0   = (blockIdx.x & 1) * BN;

    // weight-gen mapping: row = tid&63, k-group = (tid>>6)*16 + j (16 per thread)
    const int wr = tid & 63;
    const int kq = tid >> 6;      // 0..3

    float4 q;
    if (MODE == 0) {
        q = g_posn[row0 + wr];
    } else {
        int r = row0 + wr;
        float x = qraw[3 * r], y = qraw[3 * r + 1], z = qraw[3 * r + 2];
        q = make_float4(x, y, z, x * x + y * y + z * z);
    }
    const float4* kp_arr = (MODE == 0) ? g_embn : g_npe;
    const __half* Bg = (MODE == 0) ? g_FT : g_MT;

    // ldmatrix lane offsets
    const uint32_t arow  = (uint32_t)((lane & 15) * 144 + (lane >> 4) * 16);
    const uint32_t bkoff = (uint32_t)((lane & 7) * 512 + ((lane >> 3) & 1) * 4096);
    const uint32_t bxor  = (uint32_t)((lane & 7) << 4);
    const uint32_t bnb   = (uint32_t)(wid * 64 + (lane >> 4) * 16);   // warp's 32-col strip

    float acc[4][4][4];     // [m16 subtile][n8 subtile][frag]
#pragma unroll
    for (int a = 0; a < 4; a++)
#pragma unroll
        for (int b = 0; b < 4; b++)
#pragma unroll
            for (int c = 0; c < 4; c++) acc[a][b][c] = 0.f;
    float s_part = 0.f;

    auto fill = [&](int kt, int buf) {
        const int k0 = kt * BK;
        // B tile: 64 rows x 256 fp16 = 2048 16B-chunks, 8 per thread
        const uint32_t base = sb + SM_B + buf * B_BUF;
#pragma unroll
        for (int i = 0; i < 8; i++) {
            int c = tid + i * NTH;            // 0..2047
            int k = c >> 5, n8 = c & 31;
            uint32_t dst = base + (uint32_t)(k * 512 + ((n8 * 16) ^ ((k & 7) << 4)));
            cp16(dst, Bg + (size_t)(k0 + k) * FDIM + n0 + n8 * 8);
        }
        CP_COMMIT();
        // weights: 16 per thread; sum the ROUNDED values in fp32
        uint32_t hp[8];
#pragma unroll
        for (int j2 = 0; j2 < 8; j2++) {
            float w0, w1;
#pragma unroll
            for (int u = 0; u < 2; u++) {
                float4 kp = __ldg(&kp_arr[k0 + kq * 16 + j2 * 2 + u]);
                float d = fmaf(q.x, kp.x, fmaf(q.y, kp.y, q.z * kp.z));
                float w;
                if (MODE == 0) w = __expf(d);
                else           w = __expf(-sqrtf(fmaxf(q.w + kp.w - 2.f * d, EPSD)));
                if (u == 0) w0 = w; else w1 = w;
            }
            __half h0 = __float2half_rn(w0), h1 = __float2half_rn(w1);
            s_part += __half2float(h0) + __half2float(h1);
            hp[j2] = ((uint32_t)__half_as_ushort(h1) << 16) | __half_as_ushort(h0);
        }
        uint32_t aoff = (uint32_t)(wr * 144 + kq * 32);
        *(uint4*)(smem + SM_A + buf * A_BUF + aoff)      = make_uint4(hp[0], hp[1], hp[2], hp[3]);
        *(uint4*)(smem + SM_A + buf * A_BUF + aoff + 16) = make_uint4(hp[4], hp[5], hp[6], hp[7]);
    };

    fill(0, 0);
    CP_WAIT0();
    __syncthreads();

    for (int kt = 0; kt < NTK; kt++) {
        const int buf = kt & 1;
        if (kt + 1 < NTK) fill(kt + 1, buf ^ 1);

        const uint32_t Abase = sb + SM_A + buf * A_BUF;
        const uint32_t Bbase = sb + SM_B + buf * B_BUF;
#pragma unroll
        for (int kk = 0; kk < 4; kk++) {
            // B frags for this warp's 32 cols: 2 n16 groups
            uint32_t bh[2][4];
#pragma unroll
            for (int p = 0; p < 2; p++) {
                uint32_t byte0 = (bnb + p * 32) ^ bxor;
                ldsm_x4t(bh[p], Bbase + kk * 8192 + bkoff + byte0);
            }
            // A frags for all 64 rows
            uint32_t ah[4][4];
#pragma unroll
            for (int mi = 0; mi < 4; mi++)
                ldsm_x4(ah[mi], Abase + mi * 2304 + kk * 32 + arow);
#pragma unroll
            for (int mi = 0; mi < 4; mi++)
#pragma unroll
                for (int p = 0; p < 2; p++)
#pragma unroll
                    for (int qn = 0; qn < 2; qn++)
                        mma16816(acc[mi][p * 2 + qn], ah[mi], &bh[p][qn * 2]);
        }
        CP_WAIT0();
        __syncthreads();
    }

    // exact fp32 row sums of rounded weights -> inverse
    *(float*)(smem + SM_RED + (kq * 64 + wr) * 4) = s_part;
    __syncthreads();
    if (tid < BM) {
        float s = 0.f;
#pragma unroll
        for (int k = 0; k < 4; k++) s += *(float*)(smem + SM_RED + (k * 64 + tid) * 4);
        *(float*)(smem + SM_FIN + tid * 4) = 1.0f / s;
    }
    __syncthreads();

    // epilogue: warp covers rows mi*16 + {lane>>2, +8}, cols wid*32 + ni*8
    float* Cbase = (MODE == 0) ? g_memory : CoutQ;
    const int ncol0 = n0 + wid * 32 + (lane & 3) * 2;
#pragma unroll
    for (int mi = 0; mi < 4; mi++) {
        int r0 = mi * 16 + (lane >> 2);
        int r1 = r0 + 8;
        float inv0 = *(float*)(smem + SM_FIN + r0 * 4);
        float inv1 = *(float*)(smem + SM_FIN + r1 * 4);
        float* C0 = Cbase + (size_t)(row0 + r0) * FDIM + ncol0;
        float* C1 = Cbase + (size_t)(row0 + r1) * FDIM + ncol0;
#pragma unroll
        for (int ni = 0; ni < 4; ni++) {
            *(float2*)(C0 + ni * 8) = make_float2(acc[mi][ni][0] * inv0, acc[mi][ni][1] * inv0);
            *(float2*)(C1 + ni * 8) = make_float2(acc[mi][ni][2] * inv1, acc[mi][ni][3] * inv1);
        }
    }
}

// ---------------- launch ----------------
extern "C" void kernel_launch(void* const* d_in, const int* in_sizes, int n_in,
                              void* d_out, int out_size) {
    (void)in_sizes; (void)n_in; (void)out_size;
    const float* features  = (const float*)d_in[0];  // [8192, 512]
    const float* positions = (const float*)d_in[1];  // [8192, 3]
    const float* queries   = (const float*)d_in[2];  // [32768, 3]
    const float* pemb      = (const float*)d_in[3];  // [8192, 3]

    cudaFuncSetAttribute(mma_gemm<0>, cudaFuncAttributeMaxDynamicSharedMemorySize, SMEM_TOTAL);
    cudaFuncSetAttribute(mma_gemm<1>, cudaFuncAttributeMaxDynamicSharedMemorySize, SMEM_TOTAL);

    prep_kernel<<<MMEM / 256, 256>>>(positions, pemb);
    split_kernel<0><<<(MMEM * FDIM / 8) / 256, 256>>>(features);
    posemb_kernel<<<MMEM / 8, 256>>>();
    mma_gemm<0><<<(MMEM / BM) * 2, NTH, SMEM_TOTAL>>>(nullptr, nullptr);
    split_kernel<1><<<(MMEM * FDIM / 8) / 256, 256>>>(nullptr);
    mma_gemm<1><<<(NQ / BM) * 2, NTH, SMEM_TOTAL>>>(queries, (float*)d_out);
}

// round 15
// speedup vs baseline: 4.6229x; 1.0098x over previous
#include <cuda_runtime.h>
#include <cuda_fp16.h>
#include <cstdint>

#define MMEM 8192
#define FDIM 512
#define NQ   32768
#define EPSD 1e-12f

#define BM 64
#define BN 256
#define BK 64
#define NTH 256
#define NTK (MMEM / BK)     // 128 k-tiles

// ---- smem byte offsets ----
// A[buf]: 64 rows x 144B (64 fp16 = 128B data + 16B pad) = 9216 per buf
#define SM_A    0
#define A_BUF   9216
// B[buf]: 64 rows x 512B (256 fp16) = 32768 per buf (single fp16 plane)
#define SM_B    18432
#define B_BUF   32768
#define SM_RED  83968       // 4*64 floats
#define SM_FIN  84992       // 64 floats
#define SMEM_TOTAL 85248

// ---------------- device scratch ----------------
__device__ float4 g_posn[MMEM];
__device__ float4 g_embn[MMEM];
__device__ float4 g_pos4[MMEM];
__device__ float4 g_npe[MMEM];
__device__ float  g_memory[MMEM * FDIM];
__device__ __half g_FT[MMEM * FDIM];
__device__ __half g_MT[MMEM * FDIM];

// ---------------- PTX helpers ----------------
__device__ __forceinline__ uint32_t smem_u32(const void* p) {
    uint32_t a;
    asm("{ .reg .u64 t; cvta.to.shared.u64 t, %1; cvt.u32.u64 %0, t; }" : "=r"(a) : "l"(p));
    return a;
}
__device__ __forceinline__ void ldsm_x4(uint32_t* r, uint32_t addr) {
    asm volatile("ldmatrix.sync.aligned.m8n8.x4.shared.b16 {%0,%1,%2,%3}, [%4];"
        : "=r"(r[0]), "=r"(r[1]), "=r"(r[2]), "=r"(r[3]) : "r"(addr));
}
__device__ __forceinline__ void ldsm_x4t(uint32_t* r, uint32_t addr) {
    asm volatile("ldmatrix.sync.aligned.m8n8.x4.trans.shared.b16 {%0,%1,%2,%3}, [%4];"
        : "=r"(r[0]), "=r"(r[1]), "=r"(r[2]), "=r"(r[3]) : "r"(addr));
}
__device__ __forceinline__ void mma16816(float* c, const uint32_t* a, const uint32_t* b) {
    asm volatile("mma.sync.aligned.m16n8k16.row.col.f32.f16.f16.f32 "
        "{%0,%1,%2,%3}, {%4,%5,%6,%7}, {%8,%9}, {%0,%1,%2,%3};"
        : "+f"(c[0]), "+f"(c[1]), "+f"(c[2]), "+f"(c[3])
        : "r"(a[0]), "r"(a[1]), "r"(a[2]), "r"(a[3]), "r"(b[0]), "r"(b[1]));
}
// one-op packed fp32x2 -> fp16x2 (lo = second source)
__device__ __forceinline__ uint32_t cvt_f16x2(float lo, float hi) {
    uint32_t r;
    asm("cvt.rn.f16x2.f32 %0, %1, %2;" : "=r"(r) : "f"(hi), "f"(lo));
    return r;
}
__device__ __forceinline__ void cp16(uint32_t dst, const void* src) {
    asm volatile("cp.async.cg.shared.global [%0], [%1], 16;" :: "r"(dst), "l"(src) : "memory");
}
#define CP_COMMIT() asm volatile("cp.async.commit_group;" ::: "memory")
#define CP_WAIT0()  asm volatile("cp.async.wait_group 0;" ::: "memory")

// ---------------- prep: normalize ----------------
__global__ void prep_kernel(const float* __restrict__ pos, const float* __restrict__ emb) {
    int i = blockIdx.x * blockDim.x + threadIdx.x;
    if (i >= MMEM) return;
    float x = pos[3 * i], y = pos[3 * i + 1], z = pos[3 * i + 2];
    float inv = rsqrtf(x * x + y * y + z * z);
    g_posn[i] = make_float4(x * inv, y * inv, z * inv, 0.f);
    g_pos4[i] = make_float4(x, y, z, 0.f);
    float a = emb[3 * i], b = emb[3 * i + 1], c = emb[3 * i + 2];
    float inv2 = rsqrtf(a * a + b * b + c * c);
    g_embn[i] = make_float4(a * inv2, b * inv2, c * inv2, 0.f);
}

// ---------------- convert: fp32[k][n] -> fp16 [k][n] ----------------
template <int SRC>
__global__ void split_kernel(const float* __restrict__ srcArg) {
    int id = blockIdx.x * blockDim.x + threadIdx.x;   // MMEM*FDIM/8 threads
    const float4* S = (const float4*)((SRC == 0) ? srcArg : (const float*)g_memory);
    __half* Dh = (SRC == 0) ? g_FT : g_MT;
    float4 v0 = S[id * 2], v1 = S[id * 2 + 1];
    uint32_t ph[4];
    ph[0] = cvt_f16x2(v0.x, v0.y);
    ph[1] = cvt_f16x2(v0.z, v0.w);
    ph[2] = cvt_f16x2(v1.x, v1.y);
    ph[3] = cvt_f16x2(v1.z, v1.w);
    *(uint4*)&Dh[(size_t)id * 8] = make_uint4(ph[0], ph[1], ph[2], ph[3]);
}

// ---------------- new_pos_emb (self-normalizing, 8 rows/block) ----------------
__global__ void posemb_kernel() {
    const int i0 = blockIdx.x * 8;
    const int t = threadIdx.x;
    float4 pn[8];
#pragma unroll
    for (int r = 0; r < 8; r++) pn[r] = g_posn[i0 + r];
    float ax[8] = {}, ay[8] = {}, az[8] = {}, as[8] = {};
    for (int j = t; j < MMEM; j += 256) {
        float4 en = g_embn[j];
        float4 p = g_pos4[j];
#pragma unroll
        for (int r = 0; r < 8; r++) {
            float w = __expf(pn[r].x * en.x + pn[r].y * en.y + pn[r].z * en.z);
            ax[r] = fmaf(w, p.x, ax[r]);
            ay[r] = fmaf(w, p.y, ay[r]);
            az[r] = fmaf(w, p.z, az[r]);
            as[r] += w;
        }
    }
    __shared__ float red[8][4][8];
    const int lane = t & 31, warp = t >> 5;
#pragma unroll
    for (int r = 0; r < 8; r++) {
        float v[4] = {ax[r], ay[r], az[r], as[r]};
#pragma unroll
        for (int c = 0; c < 4; c++) {
#pragma unroll
            for (int s = 16; s > 0; s >>= 1) v[c] += __shfl_down_sync(0xffffffffu, v[c], s);
            if (lane == 0) red[r][c][warp] = v[c];
        }
    }
    __syncthreads();
    if (t < 8) {
        float sx = 0, sy = 0, sz = 0, ss = 0;
#pragma unroll
        for (int w = 0; w < 8; w++) { sx += red[t][0][w]; sy += red[t][1][w]; sz += red[t][2][w]; ss += red[t][3][w]; }
        float inv = 1.0f / ss;
        float x = sx * inv, y = sy * inv, z = sz * inv;
        g_npe[i0 + t] = make_float4(x, y, z, x * x + y * y + z * z);
    }
}

// ---------------- fused softmax-GEMM on mma.sync (HMMA) ----------------
// C[BM x BN] = rownorm(Wfp16) @ Bfp16 (single term). Normalizer = exact fp32
// sum of the UNROUNDED weights (round-to-nearest is unbiased; residual error
// ~2^-11/sqrt(N_eff) is negligible). Packed cvt.rn.f16x2 for A fragments.
template <int MODE>
__global__ __launch_bounds__(NTH, 2)
void mma_gemm(const float* __restrict__ qraw, float* __restrict__ CoutQ) {
    extern __shared__ __align__(1024) char smem[];
    const uint32_t sb = smem_u32(smem);
    const int tid = threadIdx.x;
    const int wid = tid >> 5, lane = tid & 31;
    const int row0 = (blockIdx.x >> 1) * BM;
    const int n0   = (blockIdx.x & 1) * BN;

    // weight-gen mapping: row = tid&63, k-group = (tid>>6)*16 + j (16 per thread)
    const int wr = tid & 63;
    const int kq = tid >> 6;      // 0..3

    float4 q;
    if (MODE == 0) {
        q = g_posn[row0 + wr];
    } else {
        int r = row0 + wr;
        float x = qraw[3 * r], y = qraw[3 * r + 1], z = qraw[3 * r + 2];
        q = make_float4(x, y, z, x * x + y * y + z * z);
    }
    const float4* kp_arr = (MODE == 0) ? g_embn : g_npe;
    const __half* Bg = (MODE == 0) ? g_FT : g_MT;

    // ldmatrix lane offsets
    const uint32_t arow  = (uint32_t)((lane & 15) * 144 + (lane >> 4) * 16);
    const uint32_t bkoff = (uint32_t)((lane & 7) * 512 + ((lane >> 3) & 1) * 4096);
    const uint32_t bxor  = (uint32_t)((lane & 7) << 4);
    const uint32_t bnb   = (uint32_t)(wid * 64 + (lane >> 4) * 16);   // warp's 32-col strip

    float acc[4][4][4];     // [m16 subtile][n8 subtile][frag]
#pragma unroll
    for (int a = 0; a < 4; a++)
#pragma unroll
        for (int b = 0; b < 4; b++)
#pragma unroll
            for (int c = 0; c < 4; c++) acc[a][b][c] = 0.f;
    float s_part = 0.f;

    auto fill = [&](int kt, int buf) {
        const int k0 = kt * BK;
        // B tile: 64 rows x 256 fp16 = 2048 16B-chunks, 8 per thread
        const uint32_t base = sb + SM_B + buf * B_BUF;
#pragma unroll
        for (int i = 0; i < 8; i++) {
            int c = tid + i * NTH;            // 0..2047
            int k = c >> 5, n8 = c & 31;
            uint32_t dst = base + (uint32_t)(k * 512 + ((n8 * 16) ^ ((k & 7) << 4)));
            cp16(dst, Bg + (size_t)(k0 + k) * FDIM + n0 + n8 * 8);
        }
        CP_COMMIT();
        // weights: 16 per thread; fp32 sum + one packed cvt per pair
        uint32_t hp[8];
#pragma unroll
        for (int j2 = 0; j2 < 8; j2++) {
            float w0, w1;
#pragma unroll
            for (int u = 0; u < 2; u++) {
                float4 kp = __ldg(&kp_arr[k0 + kq * 16 + j2 * 2 + u]);
                float d = fmaf(q.x, kp.x, fmaf(q.y, kp.y, q.z * kp.z));
                float w;
                if (MODE == 0) w = __expf(d);
                else           w = __expf(-sqrtf(fmaxf(q.w + kp.w - 2.f * d, EPSD)));
                if (u == 0) w0 = w; else w1 = w;
            }
            s_part += w0 + w1;
            hp[j2] = cvt_f16x2(w0, w1);
        }
        uint32_t aoff = (uint32_t)(wr * 144 + kq * 32);
        *(uint4*)(smem + SM_A + buf * A_BUF + aoff)      = make_uint4(hp[0], hp[1], hp[2], hp[3]);
        *(uint4*)(smem + SM_A + buf * A_BUF + aoff + 16) = make_uint4(hp[4], hp[5], hp[6], hp[7]);
    };

    fill(0, 0);
    CP_WAIT0();
    __syncthreads();

    for (int kt = 0; kt < NTK; kt++) {
        const int buf = kt & 1;
        if (kt + 1 < NTK) fill(kt + 1, buf ^ 1);

        const uint32_t Abase = sb + SM_A + buf * A_BUF;
        const uint32_t Bbase = sb + SM_B + buf * B_BUF;
#pragma unroll
        for (int kk = 0; kk < 4; kk++) {
            // B frags for this warp's 32 cols: 2 n16 groups
            uint32_t bh[2][4];
#pragma unroll
            for (int p = 0; p < 2; p++) {
                uint32_t byte0 = (bnb + p * 32) ^ bxor;
                ldsm_x4t(bh[p], Bbase + kk * 8192 + bkoff + byte0);
            }
            // A frags for all 64 rows
            uint32_t ah[4][4];
#pragma unroll
            for (int mi = 0; mi < 4; mi++)
                ldsm_x4(ah[mi], Abase + mi * 2304 + kk * 32 + arow);
#pragma unroll
            for (int mi = 0; mi < 4; mi++)
#pragma unroll
                for (int p = 0; p < 2; p++)
#pragma unroll
                    for (int qn = 0; qn < 2; qn++)
                        mma16816(acc[mi][p * 2 + qn], ah[mi], &bh[p][qn * 2]);
        }
        CP_WAIT0();
        __syncthreads();
    }

    // exact fp32 row sums -> inverse
    *(float*)(smem + SM_RED + (kq * 64 + wr) * 4) = s_part;
    __syncthreads();
    if (tid < BM) {
        float s = 0.f;
#pragma unroll
        for (int k = 0; k < 4; k++) s += *(float*)(smem + SM_RED + (k * 64 + tid) * 4);
        *(float*)(smem + SM_FIN + tid * 4) = 1.0f / s;
    }
    __syncthreads();

    // epilogue: warp covers rows mi*16 + {lane>>2, +8}, cols wid*32 + ni*8
    float* Cbase = (MODE == 0) ? g_memory : CoutQ;
    const int ncol0 = n0 + wid * 32 + (lane & 3) * 2;
#pragma unroll
    for (int mi = 0; mi < 4; mi++) {
        int r0 = mi * 16 + (lane >> 2);
        int r1 = r0 + 8;
        float inv0 = *(float*)(smem + SM_FIN + r0 * 4);
        float inv1 = *(float*)(smem + SM_FIN + r1 * 4);
        float* C0 = Cbase + (size_t)(row0 + r0) * FDIM + ncol0;
        float* C1 = Cbase + (size_t)(row0 + r1) * FDIM + ncol0;
#pragma unroll
        for (int ni = 0; ni < 4; ni++) {
            *(float2*)(C0 + ni * 8) = make_float2(acc[mi][ni][0] * inv0, acc[mi][ni][1] * inv0);
            *(float2*)(C1 + ni * 8) = make_float2(acc[mi][ni][2] * inv1, acc[mi][ni][3] * inv1);
        }
    }
}

// ---------------- launch ----------------
extern "C" void kernel_launch(void* const* d_in, const int* in_sizes, int n_in,
                              void* d_out, int out_size) {
    (void)in_sizes; (void)n_in; (void)out_size;
    const float* features  = (const float*)d_in[0];  // [8192, 512]
    const float* positions = (const float*)d_in[1];  // [8192, 3]
    const float* queries   = (const float*)d_in[2];  // [32768, 3]
    const float* pemb      = (const float*)d_in[3];  // [8192, 3]

    cudaFuncSetAttribute(mma_gemm<0>, cudaFuncAttributeMaxDynamicSharedMemorySize, SMEM_TOTAL);
    cudaFuncSetAttribute(mma_gemm<1>, cudaFuncAttributeMaxDynamicSharedMemorySize, SMEM_TOTAL);

    prep_kernel<<<MMEM / 256, 256>>>(positions, pemb);
    split_kernel<0><<<(MMEM * FDIM / 8) / 256, 256>>>(features);
    posemb_kernel<<<MMEM / 8, 256>>>();
    mma_gemm<0><<<(MMEM / BM) * 2, NTH, SMEM_TOTAL>>>(nullptr, nullptr);
    split_kernel<1><<<(MMEM * FDIM / 8) / 256, 256>>>(nullptr);
    mma_gemm<1><<<(NQ / BM) * 2, NTH, SMEM_TOTAL>>>(queries, (float*)d_out);
}